// round 1
// baseline (speedup 1.0000x reference)
#include <cuda_runtime.h>
#include <cstdint>

// Problem constants (fixed by the dataset)
#define BDIM   16384   // batch
#define FDIM   256     // features
#define BOND   16
#define NFREQ  4
#define DIN0   (1 + 2*NFREQ)   // 9

// ---------------- scratch buffers (no cudaMalloc allowed) ----------------
__device__ float g_xT[FDIM * BDIM];                  // 16 MB  : x transposed (F, B)
__device__ float g_bufA[128 * BDIM * BOND];          // 128 MB : ping
__device__ float g_bufB[64  * BDIM * BOND];          // 64 MB  : pong

// ---------------- f32x2 packed-FMA helpers (Blackwell) -------------------
__device__ __forceinline__ unsigned long long ffma2(unsigned long long a,
                                                    unsigned long long b,
                                                    unsigned long long c) {
    unsigned long long d;
    asm("fma.rn.f32x2 %0, %1, %2, %3;" : "=l"(d) : "l"(a), "l"(b), "l"(c));
    return d;
}
__device__ __forceinline__ unsigned long long pack2(float x, float y) {
    unsigned long long r;
    asm("mov.b64 %0, {%1, %2};" : "=l"(r) : "f"(x), "f"(y));
    return r;
}
__device__ __forceinline__ float2 unpack2(unsigned long long v) {
    float2 f;
    asm("mov.b64 {%0, %1}, %2;" : "=f"(f.x), "=f"(f.y) : "l"(v));
    return f;
}

// ---------------- x transpose: (B,F) -> (F,B), coalesced both sides ------
__global__ __launch_bounds__(256) void tt_transpose(const float* __restrict__ x,
                                                    float* __restrict__ xT) {
    __shared__ float tile[32][33];
    const int c0 = blockIdx.x * 32;   // feature tile
    const int r0 = blockIdx.y * 32;   // batch tile
    #pragma unroll
    for (int k = 0; k < 4; ++k) {
        int r = r0 + threadIdx.y + 8 * k;
        tile[threadIdx.y + 8 * k][threadIdx.x] = x[(size_t)r * FDIM + c0 + threadIdx.x];
    }
    __syncthreads();
    #pragma unroll
    for (int k = 0; k < 4; ++k) {
        int c = c0 + threadIdx.y + 8 * k;
        xT[(size_t)c * BDIM + r0 + threadIdx.x] = tile[threadIdx.x][threadIdx.y + 8 * k];
    }
}

// ---------------- level 0: Fourier feats + 9x9x16 bilinear ---------------
// grid: (128 pairs, B/256), block 256. out layout (128, B, 16).
__global__ __launch_bounds__(256, 4) void tt_level0(const float* __restrict__ xT,
                                                    const float* __restrict__ fminp,
                                                    const float* __restrict__ W0,
                                                    float* __restrict__ out) {
    __shared__ __align__(16) float sW[DIN0 * DIN0 * BOND];   // 1296 floats
    const int p   = blockIdx.x;
    const int tid = threadIdx.x;

    // cooperative W copy (324 float4)
    {
        const float4* wg  = reinterpret_cast<const float4*>(W0 + (size_t)p * (DIN0 * DIN0 * BOND));
        float4*       ws4 = reinterpret_cast<float4*>(sW);
        for (int k = tid; k < (DIN0 * DIN0 * BOND) / 4; k += 256) ws4[k] = wg[k];
    }
    __syncthreads();

    const int   b    = blockIdx.y * 256 + tid;
    const float fmin = *fminp;
    const float xl   = xT[(size_t)(2 * p)     * BDIM + b];
    const float xr   = xT[(size_t)(2 * p + 1) * BDIM + b];

    float l[DIN0], r[DIN0];
    {
        float a = xl * fmin;
        float s1, c1; sincosf(a, &s1, &c1);
        float s2 = s1 * c1 + c1 * s1, c2 = c1 * c1 - s1 * s1;
        float s3 = s2 * c1 + c2 * s1, c3 = c2 * c1 - s2 * s1;
        float s4 = s3 * c1 + c3 * s1, c4 = c3 * c1 - s3 * s1;
        l[0] = 1.f; l[1] = s1; l[2] = s2; l[3] = s3; l[4] = s4;
        l[5] = c1;  l[6] = c2; l[7] = c3; l[8] = c4;
    }
    {
        float a = xr * fmin;
        float s1, c1; sincosf(a, &s1, &c1);
        float s2 = s1 * c1 + c1 * s1, c2 = c1 * c1 - s1 * s1;
        float s3 = s2 * c1 + c2 * s1, c3 = c2 * c1 - s2 * s1;
        float s4 = s3 * c1 + c3 * s1, c4 = c3 * c1 - s3 * s1;
        r[0] = 1.f; r[1] = s1; r[2] = s2; r[3] = s3; r[4] = s4;
        r[5] = c1;  r[6] = c2; r[7] = c3; r[8] = c4;
    }

    unsigned long long acc[8];
    #pragma unroll
    for (int k = 0; k < 8; ++k) acc[k] = 0ull;   // {0.f, 0.f}

    #pragma unroll
    for (int i = 0; i < DIN0; ++i) {
        #pragma unroll
        for (int j = 0; j < DIN0; ++j) {
            float lr = l[i] * r[j];
            unsigned long long lr2 = pack2(lr, lr);
            const ulonglong2* wv = reinterpret_cast<const ulonglong2*>(sW + (i * DIN0 + j) * BOND);
            ulonglong2 w0 = wv[0], w1 = wv[1], w2 = wv[2], w3 = wv[3];
            acc[0] = ffma2(lr2, w0.x, acc[0]);
            acc[1] = ffma2(lr2, w0.y, acc[1]);
            acc[2] = ffma2(lr2, w1.x, acc[2]);
            acc[3] = ffma2(lr2, w1.y, acc[3]);
            acc[4] = ffma2(lr2, w2.x, acc[4]);
            acc[5] = ffma2(lr2, w2.y, acc[5]);
            acc[6] = ffma2(lr2, w3.x, acc[6]);
            acc[7] = ffma2(lr2, w3.y, acc[7]);
        }
    }

    float4* op = reinterpret_cast<float4*>(out + ((size_t)p * BDIM + b) * BOND);
    #pragma unroll
    for (int k = 0; k < 4; ++k) {
        float2 a = unpack2(acc[2 * k]);
        float2 c = unpack2(acc[2 * k + 1]);
        op[k] = make_float4(a.x, a.y, c.x, c.y);
    }
}

// ---------------- levels 1..6: 16x16x16 bilinear --------------------------
// grid: (P pairs, B/256), block 256. in (2P, B, 16) -> out (P, B, 16).
__global__ __launch_bounds__(256, 3) void tt_level_mid(const float* __restrict__ in,
                                                       const float* __restrict__ W,
                                                       float* __restrict__ out) {
    __shared__ __align__(16) float sW[BOND * BOND * BOND];   // 4096 floats = 16 KB
    const int p   = blockIdx.x;
    const int tid = threadIdx.x;

    {
        const float4* wg  = reinterpret_cast<const float4*>(W + (size_t)p * (BOND * BOND * BOND));
        float4*       ws4 = reinterpret_cast<float4*>(sW);
        #pragma unroll
        for (int k = 0; k < 4; ++k) ws4[tid + 256 * k] = wg[tid + 256 * k];
    }
    __syncthreads();

    const int b = blockIdx.y * 256 + tid;
    float l[BOND], r[BOND];
    {
        const float4* lp = reinterpret_cast<const float4*>(in + ((size_t)(2 * p)     * BDIM + b) * BOND);
        const float4* rp = reinterpret_cast<const float4*>(in + ((size_t)(2 * p + 1) * BDIM + b) * BOND);
        #pragma unroll
        for (int k = 0; k < 4; ++k) {
            float4 v = lp[k]; l[4 * k] = v.x; l[4 * k + 1] = v.y; l[4 * k + 2] = v.z; l[4 * k + 3] = v.w;
            float4 u = rp[k]; r[4 * k] = u.x; r[4 * k + 1] = u.y; r[4 * k + 2] = u.z; r[4 * k + 3] = u.w;
        }
    }

    unsigned long long acc[8];
    #pragma unroll
    for (int k = 0; k < 8; ++k) acc[k] = 0ull;

    #pragma unroll
    for (int i = 0; i < BOND; ++i) {
        #pragma unroll
        for (int j = 0; j < BOND; ++j) {
            float lr = l[i] * r[j];
            unsigned long long lr2 = pack2(lr, lr);
            const ulonglong2* wv = reinterpret_cast<const ulonglong2*>(sW + (i * BOND + j) * BOND);
            ulonglong2 w0 = wv[0], w1 = wv[1], w2 = wv[2], w3 = wv[3];
            acc[0] = ffma2(lr2, w0.x, acc[0]);
            acc[1] = ffma2(lr2, w0.y, acc[1]);
            acc[2] = ffma2(lr2, w1.x, acc[2]);
            acc[3] = ffma2(lr2, w1.y, acc[3]);
            acc[4] = ffma2(lr2, w2.x, acc[4]);
            acc[5] = ffma2(lr2, w2.y, acc[5]);
            acc[6] = ffma2(lr2, w3.x, acc[6]);
            acc[7] = ffma2(lr2, w3.y, acc[7]);
        }
    }

    float4* op = reinterpret_cast<float4*>(out + ((size_t)p * BDIM + b) * BOND);
    #pragma unroll
    for (int k = 0; k < 4; ++k) {
        float2 a = unpack2(acc[2 * k]);
        float2 c = unpack2(acc[2 * k + 1]);
        op[k] = make_float4(a.x, a.y, c.x, c.y);
    }
}

// ---------------- level 7: 16x16 -> scalar --------------------------------
__global__ __launch_bounds__(256) void tt_level7(const float* __restrict__ in,
                                                 const float* __restrict__ W,
                                                 float* __restrict__ out) {
    __shared__ float sW[BOND * BOND];
    const int tid = threadIdx.x;
    if (tid < BOND * BOND) sW[tid] = W[tid];
    __syncthreads();

    const int b = blockIdx.x * 256 + tid;
    float l[BOND], r[BOND];
    {
        const float4* lp = reinterpret_cast<const float4*>(in + ((size_t)0 * BDIM + b) * BOND);
        const float4* rp = reinterpret_cast<const float4*>(in + ((size_t)1 * BDIM + b) * BOND);
        #pragma unroll
        for (int k = 0; k < 4; ++k) {
            float4 v = lp[k]; l[4 * k] = v.x; l[4 * k + 1] = v.y; l[4 * k + 2] = v.z; l[4 * k + 3] = v.w;
            float4 u = rp[k]; r[4 * k] = u.x; r[4 * k + 1] = u.y; r[4 * k + 2] = u.z; r[4 * k + 3] = u.w;
        }
    }
    float acc = 0.f;
    #pragma unroll
    for (int i = 0; i < BOND; ++i) {
        float t = 0.f;
        #pragma unroll
        for (int j = 0; j < BOND; ++j) t = fmaf(sW[i * BOND + j], r[j], t);
        acc = fmaf(l[i], t, acc);
    }
    out[b] = acc;
}

// --------------------------------- launch ---------------------------------
extern "C" void kernel_launch(void* const* d_in, const int* in_sizes, int n_in,
                              void* d_out, int out_size) {
    const float* x    = (const float*)d_in[0];
    const float* fmin = (const float*)d_in[1];
    const float* W[8];
    for (int i = 0; i < 8; ++i) W[i] = (const float*)d_in[2 + i];

    float *xT, *bufA, *bufB;
    cudaGetSymbolAddress((void**)&xT,   g_xT);
    cudaGetSymbolAddress((void**)&bufA, g_bufA);
    cudaGetSymbolAddress((void**)&bufB, g_bufB);

    const int BT = BDIM / 256;   // 64 b-tiles

    tt_transpose<<<dim3(FDIM / 32, BDIM / 32), dim3(32, 8)>>>(x, xT);
    tt_level0  <<<dim3(128, BT), 256>>>(xT, fmin, W[0], bufA);
    tt_level_mid<<<dim3(64, BT), 256>>>(bufA, W[1], bufB);
    tt_level_mid<<<dim3(32, BT), 256>>>(bufB, W[2], bufA);
    tt_level_mid<<<dim3(16, BT), 256>>>(bufA, W[3], bufB);
    tt_level_mid<<<dim3( 8, BT), 256>>>(bufB, W[4], bufA);
    tt_level_mid<<<dim3( 4, BT), 256>>>(bufA, W[5], bufB);
    tt_level_mid<<<dim3( 2, BT), 256>>>(bufB, W[6], bufA);
    tt_level7  <<<BT, 256>>>(bufA, W[7], (float*)d_out);
}

// round 2
// speedup vs baseline: 1.3334x; 1.3334x over previous
#include <cuda_runtime.h>
#include <cstdint>

// Problem constants (fixed by the dataset)
#define BDIM   16384   // batch
#define FDIM   256     // features
#define BOND   16
#define NFREQ  4
#define DIN0   (1 + 2*NFREQ)   // 9

// ---------------- scratch buffers (no cudaMalloc allowed) ----------------
__device__ float g_xT[FDIM * BDIM];                  // 16 MB  : x transposed (F, B)
__device__ float g_bufA[128 * BDIM * BOND];          // 128 MB : ping
__device__ float g_bufB[64  * BDIM * BOND];          // 64 MB  : pong

// ---------------- f32x2 packed-FMA helpers (Blackwell) -------------------
__device__ __forceinline__ unsigned long long ffma2(unsigned long long a,
                                                    unsigned long long b,
                                                    unsigned long long c) {
    unsigned long long d;
    asm("fma.rn.f32x2 %0, %1, %2, %3;" : "=l"(d) : "l"(a), "l"(b), "l"(c));
    return d;
}
__device__ __forceinline__ unsigned long long pack2(float x, float y) {
    unsigned long long r;
    asm("mov.b64 %0, {%1, %2};" : "=l"(r) : "f"(x), "f"(y));
    return r;
}
__device__ __forceinline__ float2 unpack2(unsigned long long v) {
    float2 f;
    asm("mov.b64 {%0, %1}, %2;" : "=f"(f.x), "=f"(f.y) : "l"(v));
    return f;
}

// ---------------- x transpose: (B,F) -> (F,B), coalesced both sides ------
__global__ __launch_bounds__(256) void tt_transpose(const float* __restrict__ x,
                                                    float* __restrict__ xT) {
    __shared__ float tile[32][33];
    const int c0 = blockIdx.x * 32;   // feature tile
    const int r0 = blockIdx.y * 32;   // batch tile
    #pragma unroll
    for (int k = 0; k < 4; ++k) {
        int r = r0 + threadIdx.y + 8 * k;
        tile[threadIdx.y + 8 * k][threadIdx.x] = x[(size_t)r * FDIM + c0 + threadIdx.x];
    }
    __syncthreads();
    #pragma unroll
    for (int k = 0; k < 4; ++k) {
        int c = c0 + threadIdx.y + 8 * k;
        xT[(size_t)c * BDIM + r0 + threadIdx.x] = tile[threadIdx.x][threadIdx.y + 8 * k];
    }
}

// ---------------- Fourier feature builder --------------------------------
__device__ __forceinline__ void fourier9(float xv, float fmin, float* f) {
    float a = xv * fmin;
    float s1, c1; sincosf(a, &s1, &c1);
    float s2 = s1 * c1 + c1 * s1, c2 = c1 * c1 - s1 * s1;
    float s3 = s2 * c1 + c2 * s1, c3 = c2 * c1 - s2 * s1;
    float s4 = s3 * c1 + c3 * s1, c4 = c3 * c1 - s3 * s1;
    f[0] = 1.f; f[1] = s1; f[2] = s2; f[3] = s3; f[4] = s4;
    f[5] = c1;  f[6] = c2; f[7] = c3; f[8] = c4;
}

// ---------------- level 0: Fourier feats + 9x9x16 bilinear, 2 rows/thread -
// grid: (128 pairs, B/256), block 128. out layout (128, B, 16).
__global__ __launch_bounds__(128) void tt_level0(const float* __restrict__ xT,
                                                 const float* __restrict__ fminp,
                                                 const float* __restrict__ W0,
                                                 float* __restrict__ out) {
    __shared__ __align__(16) float sW[DIN0 * DIN0 * BOND];   // 1296 floats
    const int p   = blockIdx.x;
    const int tid = threadIdx.x;

    {
        const float4* wg  = reinterpret_cast<const float4*>(W0 + (size_t)p * (DIN0 * DIN0 * BOND));
        float4*       ws4 = reinterpret_cast<float4*>(sW);
        for (int k = tid; k < (DIN0 * DIN0 * BOND) / 4; k += 128) ws4[k] = wg[k];
    }
    __syncthreads();

    const int   b0   = blockIdx.y * 256 + tid;
    const int   b1   = b0 + 128;
    const float fmin = *fminp;

    float l0[DIN0], r0[DIN0], l1[DIN0], r1[DIN0];
    fourier9(xT[(size_t)(2 * p)     * BDIM + b0], fmin, l0);
    fourier9(xT[(size_t)(2 * p + 1) * BDIM + b0], fmin, r0);
    fourier9(xT[(size_t)(2 * p)     * BDIM + b1], fmin, l1);
    fourier9(xT[(size_t)(2 * p + 1) * BDIM + b1], fmin, r1);

    unsigned long long a0[8], a1[8];
    #pragma unroll
    for (int k = 0; k < 8; ++k) { a0[k] = 0ull; a1[k] = 0ull; }

    #pragma unroll 3
    for (int i = 0; i < DIN0; ++i) {
        #pragma unroll
        for (int j = 0; j < DIN0; ++j) {
            float x0 = l0[i] * r0[j];
            float x1 = l1[i] * r1[j];
            unsigned long long p0 = pack2(x0, x0);
            unsigned long long p1 = pack2(x1, x1);
            const ulonglong2* wv = reinterpret_cast<const ulonglong2*>(sW + (i * DIN0 + j) * BOND);
            ulonglong2 w0 = wv[0], w1 = wv[1], w2 = wv[2], w3 = wv[3];
            a0[0] = ffma2(p0, w0.x, a0[0]);  a1[0] = ffma2(p1, w0.x, a1[0]);
            a0[1] = ffma2(p0, w0.y, a0[1]);  a1[1] = ffma2(p1, w0.y, a1[1]);
            a0[2] = ffma2(p0, w1.x, a0[2]);  a1[2] = ffma2(p1, w1.x, a1[2]);
            a0[3] = ffma2(p0, w1.y, a0[3]);  a1[3] = ffma2(p1, w1.y, a1[3]);
            a0[4] = ffma2(p0, w2.x, a0[4]);  a1[4] = ffma2(p1, w2.x, a1[4]);
            a0[5] = ffma2(p0, w2.y, a0[5]);  a1[5] = ffma2(p1, w2.y, a1[5]);
            a0[6] = ffma2(p0, w3.x, a0[6]);  a1[6] = ffma2(p1, w3.x, a1[6]);
            a0[7] = ffma2(p0, w3.y, a0[7]);  a1[7] = ffma2(p1, w3.y, a1[7]);
        }
    }

    float4* o0 = reinterpret_cast<float4*>(out + ((size_t)p * BDIM + b0) * BOND);
    float4* o1 = reinterpret_cast<float4*>(out + ((size_t)p * BDIM + b1) * BOND);
    #pragma unroll
    for (int k = 0; k < 4; ++k) {
        float2 u = unpack2(a0[2 * k]), v = unpack2(a0[2 * k + 1]);
        o0[k] = make_float4(u.x, u.y, v.x, v.y);
    }
    #pragma unroll
    for (int k = 0; k < 4; ++k) {
        float2 u = unpack2(a1[2 * k]), v = unpack2(a1[2 * k + 1]);
        o1[k] = make_float4(u.x, u.y, v.x, v.y);
    }
}

// ---------------- levels 1..6: 16x16x16 bilinear, 2 rows/thread -----------
// grid: (P pairs, B/256), block 128. in (2P, B, 16) -> out (P, B, 16).
__global__ __launch_bounds__(128) void tt_level_mid(const float* __restrict__ in,
                                                    const float* __restrict__ W,
                                                    float* __restrict__ out) {
    __shared__ __align__(16) float sW[BOND * BOND * BOND];   // 4096 floats = 16 KB
    const int p   = blockIdx.x;
    const int tid = threadIdx.x;

    {
        const float4* wg  = reinterpret_cast<const float4*>(W + (size_t)p * (BOND * BOND * BOND));
        float4*       ws4 = reinterpret_cast<float4*>(sW);
        #pragma unroll
        for (int k = 0; k < 8; ++k) ws4[tid + 128 * k] = wg[tid + 128 * k];
    }
    __syncthreads();

    const int b0 = blockIdx.y * 256 + tid;
    const int b1 = b0 + 128;

    float l0[BOND], r0[BOND], l1[BOND], r1[BOND];
    {
        const float4* lp0 = reinterpret_cast<const float4*>(in + ((size_t)(2 * p)     * BDIM + b0) * BOND);
        const float4* rp0 = reinterpret_cast<const float4*>(in + ((size_t)(2 * p + 1) * BDIM + b0) * BOND);
        const float4* lp1 = reinterpret_cast<const float4*>(in + ((size_t)(2 * p)     * BDIM + b1) * BOND);
        const float4* rp1 = reinterpret_cast<const float4*>(in + ((size_t)(2 * p + 1) * BDIM + b1) * BOND);
        #pragma unroll
        for (int k = 0; k < 4; ++k) {
            float4 v;
            v = lp0[k]; l0[4*k] = v.x; l0[4*k+1] = v.y; l0[4*k+2] = v.z; l0[4*k+3] = v.w;
            v = rp0[k]; r0[4*k] = v.x; r0[4*k+1] = v.y; r0[4*k+2] = v.z; r0[4*k+3] = v.w;
            v = lp1[k]; l1[4*k] = v.x; l1[4*k+1] = v.y; l1[4*k+2] = v.z; l1[4*k+3] = v.w;
            v = rp1[k]; r1[4*k] = v.x; r1[4*k+1] = v.y; r1[4*k+2] = v.z; r1[4*k+3] = v.w;
        }
    }

    unsigned long long a0[8], a1[8];
    #pragma unroll
    for (int k = 0; k < 8; ++k) { a0[k] = 0ull; a1[k] = 0ull; }

    #pragma unroll 2
    for (int i = 0; i < BOND; ++i) {
        #pragma unroll
        for (int j = 0; j < BOND; ++j) {
            float x0 = l0[i] * r0[j];
            float x1 = l1[i] * r1[j];
            unsigned long long p0 = pack2(x0, x0);
            unsigned long long p1 = pack2(x1, x1);
            const ulonglong2* wv = reinterpret_cast<const ulonglong2*>(sW + (i * BOND + j) * BOND);
            ulonglong2 w0 = wv[0], w1 = wv[1], w2 = wv[2], w3 = wv[3];
            a0[0] = ffma2(p0, w0.x, a0[0]);  a1[0] = ffma2(p1, w0.x, a1[0]);
            a0[1] = ffma2(p0, w0.y, a0[1]);  a1[1] = ffma2(p1, w0.y, a1[1]);
            a0[2] = ffma2(p0, w1.x, a0[2]);  a1[2] = ffma2(p1, w1.x, a1[2]);
            a0[3] = ffma2(p0, w1.y, a0[3]);  a1[3] = ffma2(p1, w1.y, a1[3]);
            a0[4] = ffma2(p0, w2.x, a0[4]);  a1[4] = ffma2(p1, w2.x, a1[4]);
            a0[5] = ffma2(p0, w2.y, a0[5]);  a1[5] = ffma2(p1, w2.y, a1[5]);
            a0[6] = ffma2(p0, w3.x, a0[6]);  a1[6] = ffma2(p1, w3.x, a1[6]);
            a0[7] = ffma2(p0, w3.y, a0[7]);  a1[7] = ffma2(p1, w3.y, a1[7]);
        }
    }

    float4* o0 = reinterpret_cast<float4*>(out + ((size_t)p * BDIM + b0) * BOND);
    float4* o1 = reinterpret_cast<float4*>(out + ((size_t)p * BDIM + b1) * BOND);
    #pragma unroll
    for (int k = 0; k < 4; ++k) {
        float2 u = unpack2(a0[2 * k]), v = unpack2(a0[2 * k + 1]);
        o0[k] = make_float4(u.x, u.y, v.x, v.y);
    }
    #pragma unroll
    for (int k = 0; k < 4; ++k) {
        float2 u = unpack2(a1[2 * k]), v = unpack2(a1[2 * k + 1]);
        o1[k] = make_float4(u.x, u.y, v.x, v.y);
    }
}

// ---------------- level 7: 16x16 -> scalar --------------------------------
__global__ __launch_bounds__(256) void tt_level7(const float* __restrict__ in,
                                                 const float* __restrict__ W,
                                                 float* __restrict__ out) {
    __shared__ float sW[BOND * BOND];
    const int tid = threadIdx.x;
    if (tid < BOND * BOND) sW[tid] = W[tid];
    __syncthreads();

    const int b = blockIdx.x * 256 + tid;
    float l[BOND], r[BOND];
    {
        const float4* lp = reinterpret_cast<const float4*>(in + ((size_t)0 * BDIM + b) * BOND);
        const float4* rp = reinterpret_cast<const float4*>(in + ((size_t)1 * BDIM + b) * BOND);
        #pragma unroll
        for (int k = 0; k < 4; ++k) {
            float4 v = lp[k]; l[4 * k] = v.x; l[4 * k + 1] = v.y; l[4 * k + 2] = v.z; l[4 * k + 3] = v.w;
            float4 u = rp[k]; r[4 * k] = u.x; r[4 * k + 1] = u.y; r[4 * k + 2] = u.z; r[4 * k + 3] = u.w;
        }
    }
    float acc = 0.f;
    #pragma unroll
    for (int i = 0; i < BOND; ++i) {
        float t = 0.f;
        #pragma unroll
        for (int j = 0; j < BOND; ++j) t = fmaf(sW[i * BOND + j], r[j], t);
        acc = fmaf(l[i], t, acc);
    }
    out[b] = acc;
}

// --------------------------------- launch ---------------------------------
extern "C" void kernel_launch(void* const* d_in, const int* in_sizes, int n_in,
                              void* d_out, int out_size) {
    const float* x    = (const float*)d_in[0];
    const float* fmin = (const float*)d_in[1];
    const float* W[8];
    for (int i = 0; i < 8; ++i) W[i] = (const float*)d_in[2 + i];

    float *xT, *bufA, *bufB;
    cudaGetSymbolAddress((void**)&xT,   g_xT);
    cudaGetSymbolAddress((void**)&bufA, g_bufA);
    cudaGetSymbolAddress((void**)&bufB, g_bufB);

    const int BT = BDIM / 256;   // 64 row-tiles of 256 rows (2 rows/thread, 128 thr)

    tt_transpose<<<dim3(FDIM / 32, BDIM / 32), dim3(32, 8)>>>(x, xT);
    tt_level0  <<<dim3(128, BT), 128>>>(xT, fmin, W[0], bufA);
    tt_level_mid<<<dim3(64, BT), 128>>>(bufA, W[1], bufB);
    tt_level_mid<<<dim3(32, BT), 128>>>(bufB, W[2], bufA);
    tt_level_mid<<<dim3(16, BT), 128>>>(bufA, W[3], bufB);
    tt_level_mid<<<dim3( 8, BT), 128>>>(bufB, W[4], bufA);
    tt_level_mid<<<dim3( 4, BT), 128>>>(bufA, W[5], bufB);
    tt_level_mid<<<dim3( 2, BT), 128>>>(bufB, W[6], bufA);
    tt_level7  <<<BDIM / 256, 256>>>(bufA, W[7], (float*)d_out);
}